// round 2
// baseline (speedup 1.0000x reference)
#include <cuda_runtime.h>

#define N_NODES 50000
#define N_EDGES 1600000
#define ES      32      // edge feature size
#define HS      128     // output hidden size
#define KTOT    160     // 128 + 32

// ---------------- device scratch (no allocation allowed) ----------------
__device__ int   g_count[N_NODES];
__device__ int   g_row[N_NODES + 1];
__device__ int   g_cursor[N_NODES];
__device__ int   g_eid[N_EDGES];
__device__ float g_agg[N_NODES * ES];

// ---------------- CSR build ----------------
__global__ void count_kernel(const int* __restrict__ dst) {
    int e = blockIdx.x * blockDim.x + threadIdx.x;
    if (e < N_EDGES) atomicAdd(&g_count[dst[e]], 1);
}

__global__ void scan_kernel() {
    __shared__ int s[1024];
    const int t  = threadIdx.x;
    const int CH = (N_NODES + 1023) / 1024;   // 49
    int lo = t * CH;
    int hi = lo + CH; if (hi > N_NODES) hi = N_NODES;
    int sum = 0;
    for (int i = lo; i < hi; i++) sum += g_count[i];
    s[t] = sum;
    __syncthreads();
    // Hillis-Steele inclusive scan over 1024 partials
    for (int off = 1; off < 1024; off <<= 1) {
        int v = (t >= off) ? s[t - off] : 0;
        __syncthreads();
        s[t] += v;
        __syncthreads();
    }
    int run = s[t] - sum;   // exclusive prefix for this chunk
    for (int i = lo; i < hi; i++) {
        g_row[i]    = run;
        g_cursor[i] = run;
        run += g_count[i];
    }
    if (t == 1023) g_row[N_NODES] = s[1023];
}

__global__ void scatter_kernel(const int* __restrict__ dst) {
    int e = blockIdx.x * blockDim.x + threadIdx.x;
    if (e < N_EDGES) {
        int p = atomicAdd(&g_cursor[dst[e]], 1);
        g_eid[p] = e;
    }
}

// ---------------- node-centric fused aggregation ----------------
// One warp per node. Lane layout: sub = lane>>3 (4 edge slots), q = lane&7
// (8 float4 quads covering the 32 features). Everything (esum, hk, norms,
// masked sums) stays in registers; no float atomics anywhere.
__global__ void node_kernel(const float* __restrict__ feat) {
    const int gwarp = (blockIdx.x * blockDim.x + threadIdx.x) >> 5;
    if (gwarp >= N_NODES) return;
    const int lane = threadIdx.x & 31;
    const int sub  = lane >> 3;
    const int q    = lane & 7;

    const int start = g_row[gwarp];
    const int end   = g_row[gwarp + 1];
    const int deg   = end - start;

    const float4* f4 = (const float4*)feat;

    // ---- pass 1: mean of in-edge features ----
    float4 acc = make_float4(0.f, 0.f, 0.f, 0.f);
    for (int j = start + sub; j < end; j += 4) {
        int e = g_eid[j];
        float4 f = f4[e * 8 + q];
        acc.x += f.x; acc.y += f.y; acc.z += f.z; acc.w += f.w;
    }
    // reduce across the 4 subgroups (lanes differing in bits 3,4)
    #pragma unroll
    for (int m = 8; m <= 16; m <<= 1) {
        acc.x += __shfl_xor_sync(0xffffffffu, acc.x, m);
        acc.y += __shfl_xor_sync(0xffffffffu, acc.y, m);
        acc.z += __shfl_xor_sync(0xffffffffu, acc.z, m);
        acc.w += __shfl_xor_sync(0xffffffffu, acc.w, m);
    }
    const float inv = (deg > 0) ? (1.0f / (float)deg) : 0.0f;
    float4 hk;
    hk.x = acc.x * inv; hk.y = acc.y * inv; hk.z = acc.z * inv; hk.w = acc.w * inv;

    // |hk|^2: reduce quad-partials across the 8 q lanes (bits 0..2)
    float p = hk.x * hk.x + hk.y * hk.y + hk.z * hk.z + hk.w * hk.w;
    #pragma unroll
    for (int m = 1; m <= 4; m <<= 1) p += __shfl_xor_sync(0xffffffffu, p, m);
    const float hknorm = sqrtf(p);

    // ---- pass 2: cosine-masked mean ----
    float4 sacc = make_float4(0.f, 0.f, 0.f, 0.f);
    float scnt = 0.f;
    const int iters = (deg + 3) >> 2;
    for (int it = 0; it < iters; it++) {
        const int j = start + it * 4 + sub;
        const bool valid = (j < end);
        float4 f = make_float4(0.f, 0.f, 0.f, 0.f);
        if (valid) {
            int e = g_eid[j];
            f = f4[e * 8 + q];
        }
        float pn = hk.x * f.x + hk.y * f.y + hk.z * f.z + hk.w * f.w;
        float pf = f.x * f.x + f.y * f.y + f.z * f.z + f.w * f.w;
        #pragma unroll
        for (int m = 1; m <= 4; m <<= 1) {
            pn += __shfl_xor_sync(0xffffffffu, pn, m);
            pf += __shfl_xor_sync(0xffffffffu, pf, m);
        }
        const float c = pn / (hknorm * sqrtf(pf));  // NaN when den==0 -> mask false
        if (valid && c < 0.5f) {
            sacc.x += f.x; sacc.y += f.y; sacc.z += f.z; sacc.w += f.w;
            scnt += 1.0f;
        }
    }
    // reduce masked sums/count across the 4 subgroups
    #pragma unroll
    for (int m = 8; m <= 16; m <<= 1) {
        sacc.x += __shfl_xor_sync(0xffffffffu, sacc.x, m);
        sacc.y += __shfl_xor_sync(0xffffffffu, sacc.y, m);
        sacc.z += __shfl_xor_sync(0xffffffffu, sacc.z, m);
        sacc.w += __shfl_xor_sync(0xffffffffu, sacc.w, m);
        scnt   += __shfl_xor_sync(0xffffffffu, scnt,   m);
    }
    float4 outv;
    if (scnt > 0.f) {
        const float ic = 1.0f / scnt;
        outv.x = sacc.x * ic; outv.y = sacc.y * ic;
        outv.z = sacc.z * ic; outv.w = sacc.w * ic;
    } else {
        outv = hk;
    }
    if (sub == 0) ((float4*)g_agg)[gwarp * 8 + q] = outv;
}

// ---------------- GEMM: out[N,128] = [h_in | agg] @ W^T ----------------
// Full weights transposed into 80KB smem (conflict-free float4 LDS).
// 128 threads/CTA, 64 rows x 128 cols tile, 8x8 register tile per thread.
// x streamed from gmem (2 distinct 16B addrs per warp load -> L1 broadcast).
__global__ void __launch_bounds__(128, 2)
gemm_kernel(const float* __restrict__ hin, const float* __restrict__ W,
            float* __restrict__ out) {
    extern __shared__ float wt[];   // wt[k*HS + h] = W[h*KTOT + k]
    for (int i = threadIdx.x; i < HS * KTOT; i += 128) {
        int h = i / KTOT;
        int k = i - h * KTOT;
        wt[k * HS + h] = W[i];
    }
    __syncthreads();

    const int tx = threadIdx.x & 15;    // 16 col groups of 8 -> 128 cols
    const int ty = threadIdx.x >> 4;    // 8 row groups of 8  -> 64 rows
    const int cbase = tx * 8;
    const int r0 = blockIdx.x * 64 + ty * 8;

    float acc[64];
    #pragma unroll
    for (int i = 0; i < 64; i++) acc[i] = 0.f;

    const float4* x4 = (const float4*)hin;
    // k = 0..127 from h_in
    #pragma unroll 2
    for (int k4 = 0; k4 < 32; k4++) {
        float xr[8][4];
        #pragma unroll
        for (int i = 0; i < 8; i++) {
            int r = r0 + i; if (r >= N_NODES) r = N_NODES - 1;
            *(float4*)xr[i] = x4[r * 32 + k4];
        }
        #pragma unroll
        for (int kk = 0; kk < 4; kk++) {
            const int k = k4 * 4 + kk;
            const float4 wA = *(const float4*)&wt[k * HS + cbase];
            const float4 wB = *(const float4*)&wt[k * HS + cbase + 4];
            #pragma unroll
            for (int i = 0; i < 8; i++) {
                const float x = xr[i][kk];
                acc[i*8+0] += x * wA.x; acc[i*8+1] += x * wA.y;
                acc[i*8+2] += x * wA.z; acc[i*8+3] += x * wA.w;
                acc[i*8+4] += x * wB.x; acc[i*8+5] += x * wB.y;
                acc[i*8+6] += x * wB.z; acc[i*8+7] += x * wB.w;
            }
        }
    }
    // k = 128..159 from agg
    const float4* a4 = (const float4*)g_agg;
    #pragma unroll
    for (int k4 = 0; k4 < 8; k4++) {
        float xr[8][4];
        #pragma unroll
        for (int i = 0; i < 8; i++) {
            int r = r0 + i; if (r >= N_NODES) r = N_NODES - 1;
            *(float4*)xr[i] = a4[r * 8 + k4];
        }
        #pragma unroll
        for (int kk = 0; kk < 4; kk++) {
            const int k = 128 + k4 * 4 + kk;
            const float4 wA = *(const float4*)&wt[k * HS + cbase];
            const float4 wB = *(const float4*)&wt[k * HS + cbase + 4];
            #pragma unroll
            for (int i = 0; i < 8; i++) {
                const float x = xr[i][kk];
                acc[i*8+0] += x * wA.x; acc[i*8+1] += x * wA.y;
                acc[i*8+2] += x * wA.z; acc[i*8+3] += x * wA.w;
                acc[i*8+4] += x * wB.x; acc[i*8+5] += x * wB.y;
                acc[i*8+6] += x * wB.z; acc[i*8+7] += x * wB.w;
            }
        }
    }
    #pragma unroll
    for (int i = 0; i < 8; i++) {
        const int r = r0 + i;
        if (r < N_NODES) {
            float4 o0, o1;
            o0.x = acc[i*8+0]; o0.y = acc[i*8+1]; o0.z = acc[i*8+2]; o0.w = acc[i*8+3];
            o1.x = acc[i*8+4]; o1.y = acc[i*8+5]; o1.z = acc[i*8+6]; o1.w = acc[i*8+7];
            float4* op = (float4*)(out + r * HS + cbase);
            op[0] = o0;
            op[1] = o1;
        }
    }
}

// ---------------- launcher ----------------
extern "C" void kernel_launch(void* const* d_in, const int* in_sizes, int n_in,
                              void* d_out, int out_size) {
    const float* h_in = (const float*)d_in[0];
    const float* feat = (const float*)d_in[1];
    const int*   dst  = (const int*)d_in[2];
    const float* W    = (const float*)d_in[3];
    float*       out  = (float*)d_out;

    void* cptr = nullptr;
    cudaGetSymbolAddress(&cptr, g_count);
    cudaMemsetAsync(cptr, 0, N_NODES * sizeof(int));

    count_kernel<<<(N_EDGES + 255) / 256, 256>>>(dst);
    scan_kernel<<<1, 1024>>>();
    scatter_kernel<<<(N_EDGES + 255) / 256, 256>>>(dst);
    node_kernel<<<(N_NODES * 32) / 256, 256>>>(feat);

    cudaFuncSetAttribute(gemm_kernel,
                         cudaFuncAttributeMaxDynamicSharedMemorySize,
                         HS * KTOT * (int)sizeof(float));
    gemm_kernel<<<(N_NODES + 63) / 64, 128, HS * KTOT * sizeof(float)>>>(h_in, W, out);
}

// round 3
// speedup vs baseline: 1.5057x; 1.5057x over previous
#include <cuda_runtime.h>

#define N_NODES 50000
#define N_EDGES 1600000
#define ES      32      // edge feature size
#define HS      128     // output hidden size
#define KTOT    160     // 128 + 32

// ---------------- device scratch (no allocation allowed) ----------------
__device__ int   g_count[N_NODES];
__device__ int   g_row[N_NODES + 1];
__device__ int   g_cursor[N_NODES];
__device__ int   g_eid[N_EDGES];
__device__ float g_agg[N_NODES * ES];

// ---------------- CSR build ----------------
__global__ void count_kernel(const int* __restrict__ dst) {
    int e = blockIdx.x * blockDim.x + threadIdx.x;
    if (e < N_EDGES) atomicAdd(&g_count[dst[e]], 1);
}

__global__ void scan_kernel() {
    __shared__ int s[1024];
    const int t  = threadIdx.x;
    const int CH = (N_NODES + 1023) / 1024;   // 49
    int lo = t * CH;
    int hi = lo + CH; if (hi > N_NODES) hi = N_NODES;
    int sum = 0;
    for (int i = lo; i < hi; i++) sum += g_count[i];
    s[t] = sum;
    __syncthreads();
    for (int off = 1; off < 1024; off <<= 1) {
        int v = (t >= off) ? s[t - off] : 0;
        __syncthreads();
        s[t] += v;
        __syncthreads();
    }
    int run = s[t] - sum;   // exclusive prefix for this chunk
    for (int i = lo; i < hi; i++) {
        g_row[i]    = run;
        g_cursor[i] = run;
        run += g_count[i];
    }
    if (t == 1023) g_row[N_NODES] = s[1023];
}

__global__ void scatter_kernel(const int* __restrict__ dst) {
    int e = blockIdx.x * blockDim.x + threadIdx.x;
    if (e < N_EDGES) {
        int p = atomicAdd(&g_cursor[dst[e]], 1);
        g_eid[p] = e;
    }
}

// ---------------- node-centric fused aggregation ----------------
// One warp per node. sub = lane>>3 (4 edge slots), q = lane&7 (8 float4
// quads = 32 feats). Unrolled x2 in both passes for MLP / shfl-chain ILP.
__global__ void node_kernel(const float* __restrict__ feat) {
    const int gwarp = (blockIdx.x * blockDim.x + threadIdx.x) >> 5;
    if (gwarp >= N_NODES) return;
    const int lane = threadIdx.x & 31;
    const int sub  = lane >> 3;
    const int q    = lane & 7;

    const int start = g_row[gwarp];
    const int end   = g_row[gwarp + 1];
    const int deg   = end - start;

    const float4* f4 = (const float4*)feat;

    // ---- pass 1: mean of in-edge features (2 independent chains) ----
    float4 a0 = make_float4(0.f, 0.f, 0.f, 0.f);
    float4 a1 = make_float4(0.f, 0.f, 0.f, 0.f);
    int j = start + sub;
    for (; j + 4 < end; j += 8) {
        int e0 = g_eid[j];
        int e1 = g_eid[j + 4];
        float4 f0 = f4[e0 * 8 + q];
        float4 f1 = f4[e1 * 8 + q];
        a0.x += f0.x; a0.y += f0.y; a0.z += f0.z; a0.w += f0.w;
        a1.x += f1.x; a1.y += f1.y; a1.z += f1.z; a1.w += f1.w;
    }
    if (j < end) {
        int e0 = g_eid[j];
        float4 f0 = f4[e0 * 8 + q];
        a0.x += f0.x; a0.y += f0.y; a0.z += f0.z; a0.w += f0.w;
    }
    float4 acc;
    acc.x = a0.x + a1.x; acc.y = a0.y + a1.y;
    acc.z = a0.z + a1.z; acc.w = a0.w + a1.w;
    #pragma unroll
    for (int m = 8; m <= 16; m <<= 1) {
        acc.x += __shfl_xor_sync(0xffffffffu, acc.x, m);
        acc.y += __shfl_xor_sync(0xffffffffu, acc.y, m);
        acc.z += __shfl_xor_sync(0xffffffffu, acc.z, m);
        acc.w += __shfl_xor_sync(0xffffffffu, acc.w, m);
    }
    const float inv = (deg > 0) ? (1.0f / (float)deg) : 0.0f;
    float4 hk;
    hk.x = acc.x * inv; hk.y = acc.y * inv; hk.z = acc.z * inv; hk.w = acc.w * inv;

    float p = hk.x * hk.x + hk.y * hk.y + hk.z * hk.z + hk.w * hk.w;
    #pragma unroll
    for (int m = 1; m <= 4; m <<= 1) p += __shfl_xor_sync(0xffffffffu, p, m);
    const float hknorm = sqrtf(p);

    // ---- pass 2: cosine-masked mean (2 edge-groups per iter, 4 ILP chains) ----
    float4 sacc = make_float4(0.f, 0.f, 0.f, 0.f);
    float scnt = 0.f;
    const int iters = (deg + 3) >> 2;
    for (int it = 0; it < iters; it += 2) {
        const int j0 = start + it * 4 + sub;
        const int j1 = j0 + 4;
        const bool v0 = (j0 < end);
        const bool v1 = (j1 < end);
        float4 f0 = make_float4(0.f, 0.f, 0.f, 0.f);
        float4 f1 = make_float4(0.f, 0.f, 0.f, 0.f);
        if (v0) { int e = g_eid[j0]; f0 = f4[e * 8 + q]; }
        if (v1) { int e = g_eid[j1]; f1 = f4[e * 8 + q]; }

        float pn0 = hk.x * f0.x + hk.y * f0.y + hk.z * f0.z + hk.w * f0.w;
        float pf0 = f0.x * f0.x + f0.y * f0.y + f0.z * f0.z + f0.w * f0.w;
        float pn1 = hk.x * f1.x + hk.y * f1.y + hk.z * f1.z + hk.w * f1.w;
        float pf1 = f1.x * f1.x + f1.y * f1.y + f1.z * f1.z + f1.w * f1.w;
        #pragma unroll
        for (int m = 1; m <= 4; m <<= 1) {
            pn0 += __shfl_xor_sync(0xffffffffu, pn0, m);
            pf0 += __shfl_xor_sync(0xffffffffu, pf0, m);
            pn1 += __shfl_xor_sync(0xffffffffu, pn1, m);
            pf1 += __shfl_xor_sync(0xffffffffu, pf1, m);
        }
        const float c0 = pn0 / (hknorm * sqrtf(pf0));  // NaN -> mask false
        const float c1 = pn1 / (hknorm * sqrtf(pf1));
        if (v0 && c0 < 0.5f) {
            sacc.x += f0.x; sacc.y += f0.y; sacc.z += f0.z; sacc.w += f0.w;
            scnt += 1.0f;
        }
        if (v1 && c1 < 0.5f) {
            sacc.x += f1.x; sacc.y += f1.y; sacc.z += f1.z; sacc.w += f1.w;
            scnt += 1.0f;
        }
    }
    #pragma unroll
    for (int m = 8; m <= 16; m <<= 1) {
        sacc.x += __shfl_xor_sync(0xffffffffu, sacc.x, m);
        sacc.y += __shfl_xor_sync(0xffffffffu, sacc.y, m);
        sacc.z += __shfl_xor_sync(0xffffffffu, sacc.z, m);
        sacc.w += __shfl_xor_sync(0xffffffffu, sacc.w, m);
        scnt   += __shfl_xor_sync(0xffffffffu, scnt,   m);
    }
    float4 outv;
    if (scnt > 0.f) {
        const float ic = 1.0f / scnt;
        outv.x = sacc.x * ic; outv.y = sacc.y * ic;
        outv.z = sacc.z * ic; outv.w = sacc.w * ic;
    } else {
        outv = hk;
    }
    if (sub == 0) ((float4*)g_agg)[gwarp * 8 + q] = outv;
}

// ---------------- GEMM: out[N,128] = [h_in | agg] @ W^T ----------------
// 256 threads/CTA, 128x128 tile, 8x8 register tile, weights in 80KB smem.
// 2 CTAs/SM -> 16 warps/SM (vs 8 before) to keep the fma pipe fed.
__global__ void __launch_bounds__(256, 2)
gemm_kernel(const float* __restrict__ hin, const float* __restrict__ W,
            float* __restrict__ out) {
    extern __shared__ float wt[];   // wt[k*HS + h] = W[h*KTOT + k]
    for (int i = threadIdx.x; i < HS * KTOT; i += 256) {
        int h = i / KTOT;
        int k = i - h * KTOT;
        wt[k * HS + h] = W[i];
    }
    __syncthreads();

    const int tx = threadIdx.x & 15;    // 16 col groups of 8 -> 128 cols
    const int ty = threadIdx.x >> 4;    // 16 row groups of 8 -> 128 rows
    const int cbase = tx * 8;
    const int r0 = blockIdx.x * 128 + ty * 8;

    float acc[64];
    #pragma unroll
    for (int i = 0; i < 64; i++) acc[i] = 0.f;

    const float4* x4 = (const float4*)hin;
    // k = 0..127 from h_in
    #pragma unroll 2
    for (int k4 = 0; k4 < 32; k4++) {
        float xr[8][4];
        #pragma unroll
        for (int i = 0; i < 8; i++) {
            int r = r0 + i; if (r >= N_NODES) r = N_NODES - 1;
            *(float4*)xr[i] = x4[r * 32 + k4];
        }
        #pragma unroll
        for (int kk = 0; kk < 4; kk++) {
            const int k = k4 * 4 + kk;
            const float4 wA = *(const float4*)&wt[k * HS + cbase];
            const float4 wB = *(const float4*)&wt[k * HS + cbase + 4];
            #pragma unroll
            for (int i = 0; i < 8; i++) {
                const float x = xr[i][kk];
                acc[i*8+0] += x * wA.x; acc[i*8+1] += x * wA.y;
                acc[i*8+2] += x * wA.z; acc[i*8+3] += x * wA.w;
                acc[i*8+4] += x * wB.x; acc[i*8+5] += x * wB.y;
                acc[i*8+6] += x * wB.z; acc[i*8+7] += x * wB.w;
            }
        }
    }
    // k = 128..159 from agg
    const float4* a4 = (const float4*)g_agg;
    #pragma unroll
    for (int k4 = 0; k4 < 8; k4++) {
        float xr[8][4];
        #pragma unroll
        for (int i = 0; i < 8; i++) {
            int r = r0 + i; if (r >= N_NODES) r = N_NODES - 1;
            *(float4*)xr[i] = a4[r * 8 + k4];
        }
        #pragma unroll
        for (int kk = 0; kk < 4; kk++) {
            const int k = 128 + k4 * 4 + kk;
            const float4 wA = *(const float4*)&wt[k * HS + cbase];
            const float4 wB = *(const float4*)&wt[k * HS + cbase + 4];
            #pragma unroll
            for (int i = 0; i < 8; i++) {
                const float x = xr[i][kk];
                acc[i*8+0] += x * wA.x; acc[i*8+1] += x * wA.y;
                acc[i*8+2] += x * wA.z; acc[i*8+3] += x * wA.w;
                acc[i*8+4] += x * wB.x; acc[i*8+5] += x * wB.y;
                acc[i*8+6] += x * wB.z; acc[i*8+7] += x * wB.w;
            }
        }
    }
    #pragma unroll
    for (int i = 0; i < 8; i++) {
        const int r = r0 + i;
        if (r < N_NODES) {
            float4 o0, o1;
            o0.x = acc[i*8+0]; o0.y = acc[i*8+1]; o0.z = acc[i*8+2]; o0.w = acc[i*8+3];
            o1.x = acc[i*8+4]; o1.y = acc[i*8+5]; o1.z = acc[i*8+6]; o1.w = acc[i*8+7];
            float4* op = (float4*)(out + r * HS + cbase);
            op[0] = o0;
            op[1] = o1;
        }
    }
}

// ---------------- launcher ----------------
extern "C" void kernel_launch(void* const* d_in, const int* in_sizes, int n_in,
                              void* d_out, int out_size) {
    const float* h_in = (const float*)d_in[0];
    const float* feat = (const float*)d_in[1];
    const int*   dst  = (const int*)d_in[2];
    const float* W    = (const float*)d_in[3];
    float*       out  = (float*)d_out;

    void* cptr = nullptr;
    cudaGetSymbolAddress(&cptr, g_count);
    cudaMemsetAsync(cptr, 0, N_NODES * sizeof(int));

    count_kernel<<<(N_EDGES + 255) / 256, 256>>>(dst);
    scan_kernel<<<1, 1024>>>();
    scatter_kernel<<<(N_EDGES + 255) / 256, 256>>>(dst);
    node_kernel<<<(N_NODES * 32) / 256, 256>>>(feat);

    cudaFuncSetAttribute(gemm_kernel,
                         cudaFuncAttributeMaxDynamicSharedMemorySize,
                         HS * KTOT * (int)sizeof(float));
    gemm_kernel<<<(N_NODES + 127) / 128, 256, HS * KTOT * sizeof(float)>>>(h_in, W, out);
}

// round 17
// speedup vs baseline: 1.6262x; 1.0800x over previous
#include <cuda_runtime.h>

#define N_NODES 50000
#define N_EDGES 1600000
#define ES      32      // edge feature size
#define HS      128     // output hidden size
#define KTOT    160     // 128 + 32
#define GEMM_TILES ((N_NODES + 63) / 64)   // 782 row tiles
#define GEMM_GRID  296                      // 148 SMs x 2 CTAs

// ---------------- device scratch (no allocation allowed) ----------------
__device__ int   g_count[N_NODES];
__device__ int   g_row[N_NODES + 1];
__device__ int   g_cursor[N_NODES];
__device__ int   g_eid[N_EDGES];
__device__ float g_agg[N_NODES * ES];

// ---------------- CSR build ----------------
__global__ void count_kernel(const int* __restrict__ dst) {
    int e = blockIdx.x * blockDim.x + threadIdx.x;
    if (e < N_EDGES) atomicAdd(&g_count[dst[e]], 1);
}

__global__ void scan_kernel() {
    __shared__ int s[1024];
    const int t  = threadIdx.x;
    const int CH = (N_NODES + 1023) / 1024;   // 49
    int lo = t * CH;
    int hi = lo + CH; if (hi > N_NODES) hi = N_NODES;
    int sum = 0;
    for (int i = lo; i < hi; i++) sum += g_count[i];
    s[t] = sum;
    __syncthreads();
    for (int off = 1; off < 1024; off <<= 1) {
        int v = (t >= off) ? s[t - off] : 0;
        __syncthreads();
        s[t] += v;
        __syncthreads();
    }
    int run = s[t] - sum;   // exclusive prefix for this chunk
    for (int i = lo; i < hi; i++) {
        g_row[i]    = run;
        g_cursor[i] = run;
        run += g_count[i];
    }
    if (t == 1023) g_row[N_NODES] = s[1023];
}

__global__ void scatter_kernel(const int* __restrict__ dst) {
    int e = blockIdx.x * blockDim.x + threadIdx.x;
    if (e < N_EDGES) {
        int p = atomicAdd(&g_cursor[dst[e]], 1);
        g_eid[p] = e;
    }
}

// ---------------- node-centric fused aggregation ----------------
// One warp per node. sub = lane>>3 (4 edge slots), q = lane&7 (8 float4
// quads = 32 feats). Pass 1 unrolled x4, pass 2 x2 for MLP / shfl ILP.
__global__ void node_kernel(const float* __restrict__ feat) {
    const int gwarp = (blockIdx.x * blockDim.x + threadIdx.x) >> 5;
    if (gwarp >= N_NODES) return;
    const int lane = threadIdx.x & 31;
    const int sub  = lane >> 3;
    const int q    = lane & 7;

    const int start = g_row[gwarp];
    const int end   = g_row[gwarp + 1];
    const int deg   = end - start;

    const float4* f4 = (const float4*)feat;

    // ---- pass 1: mean of in-edge features (4 independent chains) ----
    float4 a0 = make_float4(0.f, 0.f, 0.f, 0.f);
    float4 a1 = make_float4(0.f, 0.f, 0.f, 0.f);
    float4 a2 = make_float4(0.f, 0.f, 0.f, 0.f);
    float4 a3 = make_float4(0.f, 0.f, 0.f, 0.f);
    int j = start + sub;
    for (; j + 12 < end; j += 16) {
        int e0 = g_eid[j];
        int e1 = g_eid[j + 4];
        int e2 = g_eid[j + 8];
        int e3 = g_eid[j + 12];
        float4 f0 = f4[e0 * 8 + q];
        float4 f1 = f4[e1 * 8 + q];
        float4 f2 = f4[e2 * 8 + q];
        float4 f3 = f4[e3 * 8 + q];
        a0.x += f0.x; a0.y += f0.y; a0.z += f0.z; a0.w += f0.w;
        a1.x += f1.x; a1.y += f1.y; a1.z += f1.z; a1.w += f1.w;
        a2.x += f2.x; a2.y += f2.y; a2.z += f2.z; a2.w += f2.w;
        a3.x += f3.x; a3.y += f3.y; a3.z += f3.z; a3.w += f3.w;
    }
    for (; j < end; j += 4) {
        int e0 = g_eid[j];
        float4 f0 = f4[e0 * 8 + q];
        a0.x += f0.x; a0.y += f0.y; a0.z += f0.z; a0.w += f0.w;
    }
    float4 acc;
    acc.x = (a0.x + a1.x) + (a2.x + a3.x);
    acc.y = (a0.y + a1.y) + (a2.y + a3.y);
    acc.z = (a0.z + a1.z) + (a2.z + a3.z);
    acc.w = (a0.w + a1.w) + (a2.w + a3.w);
    #pragma unroll
    for (int m = 8; m <= 16; m <<= 1) {
        acc.x += __shfl_xor_sync(0xffffffffu, acc.x, m);
        acc.y += __shfl_xor_sync(0xffffffffu, acc.y, m);
        acc.z += __shfl_xor_sync(0xffffffffu, acc.z, m);
        acc.w += __shfl_xor_sync(0xffffffffu, acc.w, m);
    }
    const float inv = (deg > 0) ? (1.0f / (float)deg) : 0.0f;
    float4 hk;
    hk.x = acc.x * inv; hk.y = acc.y * inv; hk.z = acc.z * inv; hk.w = acc.w * inv;

    float p = hk.x * hk.x + hk.y * hk.y + hk.z * hk.z + hk.w * hk.w;
    #pragma unroll
    for (int m = 1; m <= 4; m <<= 1) p += __shfl_xor_sync(0xffffffffu, p, m);
    const float hknorm = sqrtf(p);

    // ---- pass 2: cosine-masked mean (2 edge-groups per iter, 4 ILP chains) ----
    float4 sacc = make_float4(0.f, 0.f, 0.f, 0.f);
    float scnt = 0.f;
    const int iters = (deg + 3) >> 2;
    for (int it = 0; it < iters; it += 2) {
        const int j0 = start + it * 4 + sub;
        const int j1 = j0 + 4;
        const bool v0 = (j0 < end);
        const bool v1 = (j1 < end);
        float4 f0 = make_float4(0.f, 0.f, 0.f, 0.f);
        float4 f1 = make_float4(0.f, 0.f, 0.f, 0.f);
        if (v0) { int e = g_eid[j0]; f0 = f4[e * 8 + q]; }
        if (v1) { int e = g_eid[j1]; f1 = f4[e * 8 + q]; }

        float pn0 = hk.x * f0.x + hk.y * f0.y + hk.z * f0.z + hk.w * f0.w;
        float pf0 = f0.x * f0.x + f0.y * f0.y + f0.z * f0.z + f0.w * f0.w;
        float pn1 = hk.x * f1.x + hk.y * f1.y + hk.z * f1.z + hk.w * f1.w;
        float pf1 = f1.x * f1.x + f1.y * f1.y + f1.z * f1.z + f1.w * f1.w;
        #pragma unroll
        for (int m = 1; m <= 4; m <<= 1) {
            pn0 += __shfl_xor_sync(0xffffffffu, pn0, m);
            pf0 += __shfl_xor_sync(0xffffffffu, pf0, m);
            pn1 += __shfl_xor_sync(0xffffffffu, pn1, m);
            pf1 += __shfl_xor_sync(0xffffffffu, pf1, m);
        }
        const float c0 = pn0 / (hknorm * sqrtf(pf0));  // NaN -> mask false
        const float c1 = pn1 / (hknorm * sqrtf(pf1));
        if (v0 && c0 < 0.5f) {
            sacc.x += f0.x; sacc.y += f0.y; sacc.z += f0.z; sacc.w += f0.w;
            scnt += 1.0f;
        }
        if (v1 && c1 < 0.5f) {
            sacc.x += f1.x; sacc.y += f1.y; sacc.z += f1.z; sacc.w += f1.w;
            scnt += 1.0f;
        }
    }
    #pragma unroll
    for (int m = 8; m <= 16; m <<= 1) {
        sacc.x += __shfl_xor_sync(0xffffffffu, sacc.x, m);
        sacc.y += __shfl_xor_sync(0xffffffffu, sacc.y, m);
        sacc.z += __shfl_xor_sync(0xffffffffu, sacc.z, m);
        sacc.w += __shfl_xor_sync(0xffffffffu, sacc.w, m);
        scnt   += __shfl_xor_sync(0xffffffffu, scnt,   m);
    }
    float4 outv;
    if (scnt > 0.f) {
        const float ic = 1.0f / scnt;
        outv.x = sacc.x * ic; outv.y = sacc.y * ic;
        outv.z = sacc.z * ic; outv.w = sacc.w * ic;
    } else {
        outv = hk;
    }
    if (sub == 0) ((float4*)g_agg)[gwarp * 8 + q] = outv;
}

// ---------------- GEMM: out[N,128] = [h_in | agg] @ W^T ----------------
// Persistent grid: 296 CTAs load the 80KB transposed weights into smem ONCE,
// then grid-stride over 782 row tiles. 256 threads/CTA, 64x128 tile,
// 4 rows x 8 cols per thread (32 accs, ~70 regs), 2 CTAs/SM.
__global__ void __launch_bounds__(256, 2)
gemm_kernel(const float* __restrict__ hin, const float* __restrict__ W,
            float* __restrict__ out) {
    extern __shared__ float wt[];   // wt[k*HS + h] = W[h*KTOT + k]
    for (int i = threadIdx.x; i < HS * KTOT; i += 256) {
        int h = i / KTOT;
        int k = i - h * KTOT;
        wt[k * HS + h] = W[i];
    }
    __syncthreads();

    const int tx = threadIdx.x & 15;    // 16 col groups of 8 -> 128 cols
    const int ty = threadIdx.x >> 4;    // 16 row groups of 4 -> 64 rows
    const int cbase = tx * 8;

    const float4* x4 = (const float4*)hin;
    const float4* a4 = (const float4*)g_agg;

    for (int tile = blockIdx.x; tile < GEMM_TILES; tile += gridDim.x) {
        const int r0 = tile * 64 + ty * 4;

        float acc[32];
        #pragma unroll
        for (int i = 0; i < 32; i++) acc[i] = 0.f;

        // k = 0..127 from h_in
        #pragma unroll 2
        for (int k4 = 0; k4 < 32; k4++) {
            float xr[4][4];
            #pragma unroll
            for (int i = 0; i < 4; i++) {
                int r = r0 + i; if (r >= N_NODES) r = N_NODES - 1;
                *(float4*)xr[i] = x4[r * 32 + k4];
            }
            #pragma unroll
            for (int kk = 0; kk < 4; kk++) {
                const int k = k4 * 4 + kk;
                const float4 wA = *(const float4*)&wt[k * HS + cbase];
                const float4 wB = *(const float4*)&wt[k * HS + cbase + 4];
                #pragma unroll
                for (int i = 0; i < 4; i++) {
                    const float x = xr[i][kk];
                    acc[i*8+0] += x * wA.x; acc[i*8+1] += x * wA.y;
                    acc[i*8+2] += x * wA.z; acc[i*8+3] += x * wA.w;
                    acc[i*8+4] += x * wB.x; acc[i*8+5] += x * wB.y;
                    acc[i*8+6] += x * wB.z; acc[i*8+7] += x * wB.w;
                }
            }
        }
        // k = 128..159 from agg
        #pragma unroll
        for (int k4 = 0; k4 < 8; k4++) {
            float xr[4][4];
            #pragma unroll
            for (int i = 0; i < 4; i++) {
                int r = r0 + i; if (r >= N_NODES) r = N_NODES - 1;
                *(float4*)xr[i] = a4[r * 8 + k4];
            }
            #pragma unroll
            for (int kk = 0; kk < 4; kk++) {
                const int k = 128 + k4 * 4 + kk;
                const float4 wA = *(const float4*)&wt[k * HS + cbase];
                const float4 wB = *(const float4*)&wt[k * HS + cbase + 4];
                #pragma unroll
                for (int i = 0; i < 4; i++) {
                    const float x = xr[i][kk];
                    acc[i*8+0] += x * wA.x; acc[i*8+1] += x * wA.y;
                    acc[i*8+2] += x * wA.z; acc[i*8+3] += x * wA.w;
                    acc[i*8+4] += x * wB.x; acc[i*8+5] += x * wB.y;
                    acc[i*8+6] += x * wB.z; acc[i*8+7] += x * wB.w;
                }
            }
        }
        #pragma unroll
        for (int i = 0; i < 4; i++) {
            const int r = r0 + i;
            if (r < N_NODES) {
                float4 o0, o1;
                o0.x = acc[i*8+0]; o0.y = acc[i*8+1]; o0.z = acc[i*8+2]; o0.w = acc[i*8+3];
                o1.x = acc[i*8+4]; o1.y = acc[i*8+5]; o1.z = acc[i*8+6]; o1.w = acc[i*8+7];
                float4* op = (float4*)(out + r * HS + cbase);
                op[0] = o0;
                op[1] = o1;
            }
        }
    }
}

// ---------------- launcher ----------------
extern "C" void kernel_launch(void* const* d_in, const int* in_sizes, int n_in,
                              void* d_out, int out_size) {
    const float* h_in = (const float*)d_in[0];
    const float* feat = (const float*)d_in[1];
    const int*   dst  = (const int*)d_in[2];
    const float* W    = (const float*)d_in[3];
    float*       out  = (float*)d_out;

    void* cptr = nullptr;
    cudaGetSymbolAddress(&cptr, g_count);
    cudaMemsetAsync(cptr, 0, N_NODES * sizeof(int));

    count_kernel<<<(N_EDGES + 255) / 256, 256>>>(dst);
    scan_kernel<<<1, 1024>>>();
    scatter_kernel<<<(N_EDGES + 255) / 256, 256>>>(dst);
    node_kernel<<<(N_NODES * 32) / 256, 256>>>(feat);

    cudaFuncSetAttribute(gemm_kernel,
                         cudaFuncAttributeMaxDynamicSharedMemorySize,
                         HS * KTOT * (int)sizeof(float));
    gemm_kernel<<<GEMM_GRID, 256, HS * KTOT * sizeof(float)>>>(h_in, W, out);
}